// round 15
// baseline (speedup 1.0000x reference)
#include <cuda.h>
#include <cuda_runtime.h>
#include <cuda_fp16.h>
#include <cuda_bf16.h>
#include <cstdint>

#define DINLINE __device__ __forceinline__

// ---------------- problem constants ----------------
static constexpr int M_TOTAL = 16384;   // 8 * 2048
static constexpr int N_TOTAL = 4096;    // out features
static constexpr int K_TOTAL = 4096;    // in features
static constexpr int NUM_GROUPS = 524288;

// ---------------- GEMM tiling: 4 warps, warp tile 64x64, TMA, occ 2 --------
static constexpr int BM = 128;
static constexpr int BN = 128;
static constexpr int BK = 64;                    // halves per k-tile (128B rows)
static constexpr int KTILES = K_TOTAL / BK;      // 64
static constexpr int STAGES = 3;
static constexpr int MT = M_TOTAL / BM;          // 128
static constexpr int NT = N_TOTAL / BN;          // 32
static constexpr int GROUP_M = 8;                // supergroup 256 CTAs <= wave
static constexpr int NTHREADS = 128;             // 4 warps (2x2)

// smem layout: barriers then 1024-aligned tile data (TMA SW128, 128B rows)
static constexpr int A_BYTES      = BM * BK * 2;                 // 16384
static constexpr int STAGE_BYTES  = 2 * A_BYTES;                 // 32768
static constexpr int SMEM_BAR     = 0;     // full[s]=s*16, empty[s]=s*16+8
static constexpr int SMEM_DATA    = 1024;
static constexpr int SMEM_TOTAL   = SMEM_DATA + STAGES * STAGE_BYTES; // 99328 (x2 CTAs ok)

// scratch (device globals: allocation-free scratch per harness rules)
__device__ __align__(1024) __half g_W[(size_t)N_TOTAL * K_TOTAL];  // 32 MB
__device__ __align__(1024) __half g_X[(size_t)M_TOTAL * K_TOTAL];  // 128 MB
__device__ __align__(128) float  g_bias[N_TOTAL];
__device__ int g_dtype_flag;   // 0 = fp32, 1 = fp16, 2 = bf16

// ---------------- PTX helpers (compute_103-safe: sm_90 baseline only) ------
DINLINE uint32_t smem_u32(const void* p) {
    uint32_t a;
    asm("{ .reg .u64 t; cvta.to.shared.u64 t, %1; cvt.u32.u64 %0, t; }" : "=r"(a) : "l"(p));
    return a;
}

DINLINE void mbar_init(uint32_t a, uint32_t cnt) {
    asm volatile("mbarrier.init.shared.b64 [%0], %1;" :: "r"(a), "r"(cnt) : "memory");
}
DINLINE void mbar_expect_tx(uint32_t a, uint32_t bytes) {
    asm volatile("mbarrier.arrive.expect_tx.shared.b64 _, [%0], %1;" :: "r"(a), "r"(bytes) : "memory");
}
DINLINE void mbar_arrive(uint32_t a) {
    asm volatile("mbarrier.arrive.shared.b64 _, [%0];" :: "r"(a) : "memory");
}
DINLINE void mbar_wait(uint32_t mbar, uint32_t parity) {
    uint32_t done;
    asm volatile("{\n\t.reg .pred p;\n\t"
                 "mbarrier.try_wait.parity.acquire.cta.shared::cta.b64 p, [%1], %2;\n\t"
                 "selp.b32 %0, 1, 0, p;\n\t}"
                 : "=r"(done) : "r"(mbar), "r"(parity) : "memory");
    if (!done) {
        asm volatile("{\n\t.reg .pred P1;\n\t"
                     "WLP_%=:\n\t"
                     "mbarrier.try_wait.parity.acquire.cta.shared::cta.b64 P1, [%0], %1, 0x989680;\n\t"
                     "@P1 bra.uni WDN_%=;\n\t"
                     "bra.uni WLP_%=;\n\t"
                     "WDN_%=:\n\t}"
                     :: "r"(mbar), "r"(parity) : "memory");
    }
}
DINLINE void tma_load_2d(uint32_t dst, const CUtensorMap* map, int x, int y, uint32_t bar) {
    asm volatile("cp.async.bulk.tensor.2d.shared::cta.global.tile.mbarrier::complete_tx::bytes "
                 "[%0], [%1, {%2, %3}], [%4];"
                 :: "r"(dst), "l"(map), "r"(x), "r"(y), "r"(bar) : "memory");
}
DINLINE void fence_proxy_async() {
    asm volatile("fence.proxy.async.shared::cta;" ::: "memory");
}

DINLINE void ldsm_x4(uint32_t* r, uint32_t addr) {
    asm volatile("ldmatrix.sync.aligned.m8n8.x4.shared.b16 {%0,%1,%2,%3}, [%4];"
                 : "=r"(r[0]), "=r"(r[1]), "=r"(r[2]), "=r"(r[3]) : "r"(addr));
}

DINLINE void mma_16816(float* d, const uint32_t* a, const uint32_t* b) {
    asm volatile("mma.sync.aligned.m16n8k16.row.col.f32.f16.f16.f32 "
                 "{%0,%1,%2,%3}, {%4,%5,%6,%7}, {%8,%9}, {%0,%1,%2,%3};"
                 : "+f"(d[0]), "+f"(d[1]), "+f"(d[2]), "+f"(d[3])
                 : "r"(a[0]), "r"(a[1]), "r"(a[2]), "r"(a[3]), "r"(b[0]), "r"(b[1]));
}

// SW128 swizzle for 128B rows: chunk c (16B) of row r lives at chunk c ^ (r&7)
DINLINE uint32_t swz_off(uint32_t row, uint32_t chunk) {
    return row * 128u + ((chunk ^ (row & 7u)) << 4);
}

// ---------------- dtype detection ----------------
// scales are uniform in [0.01, 1.0). Disambiguate fp32 / fp16 / bf16 by range.
__global__ void detect_kernel(const uint32_t* __restrict__ sc_raw) {
    uint32_t w0 = sc_raw[0], w1 = sc_raw[1], w2 = sc_raw[2], w3 = sc_raw[3];
    float f[4] = {__uint_as_float(w0), __uint_as_float(w1),
                  __uint_as_float(w2), __uint_as_float(w3)};
    bool f32ok = true;
    #pragma unroll
    for (int i = 0; i < 4; i++)
        f32ok = f32ok && isfinite(f[i]) && f[i] >= 0.004f && f[i] <= 1.1f;

    bool f16ok = true;
    uint32_t ws[4] = {w0, w1, w2, w3};
    #pragma unroll
    for (int i = 0; i < 4; i++) {
        __half lo = __ushort_as_half((unsigned short)(ws[i] & 0xFFFF));
        __half hi = __ushort_as_half((unsigned short)(ws[i] >> 16));
        float a = __half2float(lo), b = __half2float(hi);
        f16ok = f16ok && a >= 0.004f && a <= 1.02f && b >= 0.004f && b <= 1.02f;
    }
    g_dtype_flag = f32ok ? 0 : (f16ok ? 1 : 2);
}

DINLINE float load_scalar(const void* p, int idx, int flag) {
    if (flag == 0) return ((const float*)p)[idx];
    if (flag == 1) return __half2float(((const __half*)p)[idx]);
    return __bfloat162float(((const __nv_bfloat16*)p)[idx]);
}

// ---------------- prepass kernels ----------------
// 4 packed int32 per thread: one LDG.128 -> 8 halves -> one STG.128.
__global__ void __launch_bounds__(256) dequant_kernel(const int4* __restrict__ wp4,
                                                      const void* __restrict__ sc,
                                                      uint4* __restrict__ W4) {
    int t = blockIdx.x * blockDim.x + threadIdx.x;   // handles packed [4t, 4t+4)
    if (t >= NUM_GROUPS * 4) return;
    int flag = g_dtype_flag;
    int g = t >> 2;                                  // group index
    float s = load_scalar(sc, g, flag);

    int4 v = __ldcs(wp4 + t);
    const int vv[4] = {v.x, v.y, v.z, v.w};
    uint4 o;
    unsigned* ou = reinterpret_cast<unsigned*>(&o);
    #pragma unroll
    for (int i = 0; i < 4; i++) {
        float w0 = ((float)(vv[i] & 7)        * (2.0f / 7.0f) - 1.0f) * s;
        float w1 = ((float)((vv[i] >> 3) & 7) * (2.0f / 7.0f) - 1.0f) * s;
        __half2 h2 = __floats2half2_rn(w0, w1);
        ou[i] = *reinterpret_cast<unsigned*>(&h2);
    }
    size_t elem = ((size_t)(g >> 7) * K_TOTAL) + (size_t)((g & 127) << 5) + ((t & 3) << 3);
    __stcs(W4 + (elem >> 3), o);
}

__global__ void __launch_bounds__(256) bias_cvt_kernel(const void* __restrict__ bias) {
    int i = blockIdx.x * blockDim.x + threadIdx.x;
    if (i >= N_TOTAL) return;
    g_bias[i] = load_scalar(bias, i, g_dtype_flag);
}

// 2 float4 per thread -> one 16B store.
__global__ void __launch_bounds__(256) cvt_kernel(const float4* __restrict__ x,
                                                  uint4* __restrict__ xh) {
    int i = blockIdx.x * blockDim.x + threadIdx.x;
    if (i >= (M_TOTAL * K_TOTAL) / 8) return;
    float4 v0 = __ldcs(x + 2 * i);
    float4 v1 = __ldcs(x + 2 * i + 1);
    __half2 a = __floats2half2_rn(v0.x, v0.y);
    __half2 b = __floats2half2_rn(v0.z, v0.w);
    __half2 c = __floats2half2_rn(v1.x, v1.y);
    __half2 d = __floats2half2_rn(v1.z, v1.w);
    uint4 o = make_uint4(*reinterpret_cast<unsigned*>(&a),
                         *reinterpret_cast<unsigned*>(&b),
                         *reinterpret_cast<unsigned*>(&c),
                         *reinterpret_cast<unsigned*>(&d));
    __stcs(xh + i, o);
}

// ---------------- GEMM kernel: TMA producer + HMMA consumers ----------------
// 4 warps (2x2), warp tile 64x64, occ 2, fragments double-buffered across
// ksteps (registers are abundant at 128 threads/CTA: ~190 used of 256 cap).
__global__ void __launch_bounds__(NTHREADS, 2) gemm_kernel(
    const __grid_constant__ CUtensorMap tma_a,
    const __grid_constant__ CUtensorMap tma_b,
    float* __restrict__ out)           // [M, N]
{
    extern __shared__ __align__(1024) char smem[];
    const uint32_t sb = smem_u32(smem);

    const int tid = threadIdx.x;
    const int wid = tid >> 5, lid = tid & 31;
    const int warp_m = wid & 1;        // 2 warps along M (64 rows each)
    const int warp_n = wid >> 1;       // 2 warps along N (64 cols each)

    // L2-friendly grid swizzle: GROUP_M rows of tiles per super-group (256 CTAs)
    const int bid    = blockIdx.x;
    const int within = bid & (GROUP_M * NT - 1);           // 0..255
    const int mtile  = (bid >> 8) * GROUP_M + (within & (GROUP_M - 1));
    const int ntile  = within >> 3;                        // 0..31

    auto fullb  = [&](int s) { return sb + SMEM_BAR + s * 16; };
    auto emptyb = [&](int s) { return sb + SMEM_BAR + s * 16 + 8; };

    if (tid == 0) {
        #pragma unroll
        for (int s = 0; s < STAGES; s++) {
            mbar_init(fullb(s), 1);    // producer's expect_tx arrive
            mbar_init(emptyb(s), 4);   // one arrive per warp
        }
        fence_proxy_async();
    }
    __syncthreads();

    // prologue: stages 0,1 for kt=0,1
    if (tid == 0) {
        #pragma unroll
        for (int kt = 0; kt < 2; kt++) {
            uint32_t base = sb + SMEM_DATA + kt * STAGE_BYTES;
            mbar_expect_tx(fullb(kt), STAGE_BYTES);
            tma_load_2d(base,           &tma_a, kt * BK, mtile * BM, fullb(kt));
            tma_load_2d(base + A_BYTES, &tma_b, kt * BK, ntile * BN, fullb(kt));
        }
    }

    float acc[4][8][4];
    #pragma unroll
    for (int mt = 0; mt < 4; mt++)
        #pragma unroll
        for (int nt = 0; nt < 8; nt++)
            #pragma unroll
            for (int i = 0; i < 4; i++) acc[mt][nt][i] = 0.0f;

    const int a_row = warp_m * 64 + (lid & 15);                     // + mt*16
    const int a_chk = lid >> 4;                                     // + ks*2
    const int b_row = warp_n * 64 + (lid & 7) + ((lid >> 4) << 3);  // + np*16
    const int b_chk = (lid >> 3) & 1;                               // + ks*2

    auto load_frags = [&](uint32_t abase, uint32_t bbase, int ks,
                          uint32_t af[4][4], uint32_t bf[8][2]) {
        #pragma unroll
        for (int mt = 0; mt < 4; mt++)
            ldsm_x4(af[mt], abase + swz_off(a_row + mt * 16, a_chk + ks * 2));
        #pragma unroll
        for (int np = 0; np < 4; np++) {
            uint32_t r[4];
            ldsm_x4(r, bbase + swz_off(b_row + np * 16, b_chk + ks * 2));
            bf[2 * np][0] = r[0]; bf[2 * np][1] = r[1];
            bf[2 * np + 1][0] = r[2]; bf[2 * np + 1][1] = r[3];
        }
    };

    #pragma unroll 1
    for (int kt = 0; kt < KTILES; kt++) {
        const int s = kt % 3, u = kt / 3;

        // producer: issue stage for kt+2
        if (tid == 0 && kt + 2 < KTILES) {
            const int kl = kt + 2, sl = kl % 3, ul = kl / 3;
            if (ul > 0) mbar_wait(emptyb(sl), (ul - 1) & 1);
            uint32_t base = sb + SMEM_DATA + sl * STAGE_BYTES;
            mbar_expect_tx(fullb(sl), STAGE_BYTES);
            tma_load_2d(base,           &tma_a, kl * BK, mtile * BM, fullb(sl));
            tma_load_2d(base + A_BYTES, &tma_b, kl * BK, ntile * BN, fullb(sl));
        }

        mbar_wait(fullb(s), u & 1);

        const uint32_t abase = sb + SMEM_DATA + s * STAGE_BYTES;
        const uint32_t bbase = abase + A_BYTES;

        uint32_t af[2][4][4];
        uint32_t bf[2][8][2];
        load_frags(abase, bbase, 0, af[0], bf[0]);

        #pragma unroll
        for (int ks = 0; ks < 4; ks++) {
            const int cur = ks & 1, nxt = cur ^ 1;
            if (ks < 3) load_frags(abase, bbase, ks + 1, af[nxt], bf[nxt]);
            #pragma unroll
            for (int mt = 0; mt < 4; mt++)
                #pragma unroll
                for (int nt = 0; nt < 8; nt++)
                    mma_16816(acc[mt][nt], af[cur][mt], bf[cur][nt]);
        }

        if (lid == 0) mbar_arrive(emptyb(s));   // release AFTER all reads consumed
    }

    // ---- epilogue: acc + bias -> out (fp32), streaming stores -------------
    const int orow0 = mtile * BM + warp_m * 64 + (lid >> 2);
    const int ocol0 = ntile * BN + warp_n * 64 + (lid & 3) * 2;

    #pragma unroll
    for (int nt = 0; nt < 8; nt++) {
        float2 bv = *reinterpret_cast<const float2*>(&g_bias[ocol0 + nt * 8]);
        #pragma unroll
        for (int mt = 0; mt < 4; mt++) {
            int r0 = orow0 + mt * 16;
            float* p0 = out + (size_t)r0 * N_TOTAL + ocol0 + nt * 8;
            float* p1 = out + (size_t)(r0 + 8) * N_TOTAL + ocol0 + nt * 8;
            __stcs(reinterpret_cast<float2*>(p0),
                   make_float2(acc[mt][nt][0] + bv.x, acc[mt][nt][1] + bv.y));
            __stcs(reinterpret_cast<float2*>(p1),
                   make_float2(acc[mt][nt][2] + bv.x, acc[mt][nt][3] + bv.y));
        }
    }
}

// ---------------- host launcher ----------------
typedef CUresult (CUDAAPI *EncodeTiledFn)(
    CUtensorMap*, CUtensorMapDataType, cuuint32_t, void*,
    const cuuint64_t*, const cuuint64_t*, const cuuint32_t*, const cuuint32_t*,
    CUtensorMapInterleave, CUtensorMapSwizzle, CUtensorMapL2promotion, CUtensorMapFloatOOBfill);

extern "C" void kernel_launch(void* const* d_in, const int* in_sizes, int n_in,
                              void* d_out, int out_size) {
    const float* x      = (const float*)d_in[0];
    const int*   wp     = (const int*)d_in[1];
    const void*  scales = d_in[2];
    const void*  bias   = d_in[3];
    float*       out    = (float*)d_out;

    void* wptr = nullptr; cudaGetSymbolAddress(&wptr, g_W);
    void* xptr = nullptr; cudaGetSymbolAddress(&xptr, g_X);

    detect_kernel<<<1, 1>>>((const uint32_t*)scales);
    dequant_kernel<<<(NUM_GROUPS * 4 + 255) / 256, 256>>>((const int4*)wp, scales, (uint4*)wptr);
    bias_cvt_kernel<<<(N_TOTAL + 255) / 256, 256>>>(bias);
    cvt_kernel<<<((M_TOTAL * K_TOTAL) / 8 + 255) / 256, 256>>>((const float4*)x, (uint4*)xptr);

    // TMA tensormaps (host-side driver entry point; no -lcuda needed)
    EncodeTiledFn encode = nullptr;
    cudaDriverEntryPointQueryResult qres;
    cudaGetDriverEntryPointByVersion("cuTensorMapEncodeTiled", (void**)&encode, 12000,
                                     cudaEnableDefault, &qres);

    CUtensorMap ta, tb;
    {
        cuuint64_t dims[2]    = {(cuuint64_t)K_TOTAL, (cuuint64_t)M_TOTAL};
        cuuint64_t strides[1] = {(cuuint64_t)K_TOTAL * 2};
        cuuint32_t box[2]     = {(cuuint32_t)BK, (cuuint32_t)BM};   // 128B x 128 rows
        cuuint32_t estr[2]    = {1, 1};
        encode(&ta, CU_TENSOR_MAP_DATA_TYPE_FLOAT16, 2, xptr, dims, strides, box, estr,
               CU_TENSOR_MAP_INTERLEAVE_NONE, CU_TENSOR_MAP_SWIZZLE_128B,
               CU_TENSOR_MAP_L2_PROMOTION_L2_128B, CU_TENSOR_MAP_FLOAT_OOB_FILL_NONE);
    }
    {
        cuuint64_t dims[2]    = {(cuuint64_t)K_TOTAL, (cuuint64_t)N_TOTAL};
        cuuint64_t strides[1] = {(cuuint64_t)K_TOTAL * 2};
        cuuint32_t box[2]     = {(cuuint32_t)BK, (cuuint32_t)BN};
        cuuint32_t estr[2]    = {1, 1};
        encode(&tb, CU_TENSOR_MAP_DATA_TYPE_FLOAT16, 2, wptr, dims, strides, box, estr,
               CU_TENSOR_MAP_INTERLEAVE_NONE, CU_TENSOR_MAP_SWIZZLE_128B,
               CU_TENSOR_MAP_L2_PROMOTION_L2_128B, CU_TENSOR_MAP_FLOAT_OOB_FILL_NONE);
    }

    cudaFuncSetAttribute(gemm_kernel, cudaFuncAttributeMaxDynamicSharedMemorySize, SMEM_TOTAL);
    gemm_kernel<<<MT * NT, NTHREADS, SMEM_TOTAL>>>(ta, tb, out);
}

// round 16
// speedup vs baseline: 1.0076x; 1.0076x over previous
#include <cuda.h>
#include <cuda_runtime.h>
#include <cuda_fp16.h>
#include <cuda_bf16.h>
#include <cstdint>

#define DINLINE __device__ __forceinline__

// ---------------- problem constants ----------------
static constexpr int M_TOTAL = 16384;   // 8 * 2048
static constexpr int N_TOTAL = 4096;    // out features
static constexpr int K_TOTAL = 4096;    // in features
static constexpr int NUM_GROUPS = 524288;

// ---------------- GEMM tiling: 4 warps, warp tile 64x64, TMA, occ 2 --------
static constexpr int BM = 128;
static constexpr int BN = 128;
static constexpr int BK = 64;                    // halves per k-tile (128B rows)
static constexpr int KTILES = K_TOTAL / BK;      // 64
static constexpr int STAGES = 3;
static constexpr int MT = M_TOTAL / BM;          // 128
static constexpr int NT = N_TOTAL / BN;          // 32
static constexpr int GROUP_M = 8;                // supergroup 256 CTAs <= wave
static constexpr int NTHREADS = 128;             // 4 warps (2x2)

// smem layout: barriers then 1024-aligned tile data (TMA SW128, 128B rows)
static constexpr int A_BYTES      = BM * BK * 2;                 // 16384
static constexpr int STAGE_BYTES  = 2 * A_BYTES;                 // 32768
static constexpr int SMEM_BAR     = 0;     // full[s]=s*16, empty[s]=s*16+8
static constexpr int SMEM_DATA    = 1024;
static constexpr int SMEM_TOTAL   = SMEM_DATA + STAGES * STAGE_BYTES; // 99328 (x2 CTAs ok)

// prepass block partition (one fused kernel)
static constexpr int NB_CVT  = (M_TOTAL * K_TOTAL / 8) / 256;    // 32768
static constexpr int NB_DQ   = (NUM_GROUPS * 4) / 256;           // 8192
static constexpr int NB_BIAS = N_TOTAL / 256;                    // 16
static constexpr int NB_PRE  = NB_CVT + NB_DQ + NB_BIAS;

// scratch (device globals: allocation-free scratch per harness rules)
__device__ __align__(1024) __half g_W[(size_t)N_TOTAL * K_TOTAL];  // 32 MB
__device__ __align__(1024) __half g_X[(size_t)M_TOTAL * K_TOTAL];  // 128 MB
__device__ __align__(128) float  g_bias[N_TOTAL];

// ---------------- PTX helpers (compute_103-safe: sm_90 baseline only) ------
DINLINE uint32_t smem_u32(const void* p) {
    uint32_t a;
    asm("{ .reg .u64 t; cvta.to.shared.u64 t, %1; cvt.u32.u64 %0, t; }" : "=r"(a) : "l"(p));
    return a;
}

DINLINE void mbar_init(uint32_t a, uint32_t cnt) {
    asm volatile("mbarrier.init.shared.b64 [%0], %1;" :: "r"(a), "r"(cnt) : "memory");
}
DINLINE void mbar_expect_tx(uint32_t a, uint32_t bytes) {
    asm volatile("mbarrier.arrive.expect_tx.shared.b64 _, [%0], %1;" :: "r"(a), "r"(bytes) : "memory");
}
DINLINE void mbar_arrive(uint32_t a) {
    asm volatile("mbarrier.arrive.shared.b64 _, [%0];" :: "r"(a) : "memory");
}
DINLINE void mbar_wait(uint32_t mbar, uint32_t parity) {
    uint32_t done;
    asm volatile("{\n\t.reg .pred p;\n\t"
                 "mbarrier.try_wait.parity.acquire.cta.shared::cta.b64 p, [%1], %2;\n\t"
                 "selp.b32 %0, 1, 0, p;\n\t}"
                 : "=r"(done) : "r"(mbar), "r"(parity) : "memory");
    if (!done) {
        asm volatile("{\n\t.reg .pred P1;\n\t"
                     "WLP_%=:\n\t"
                     "mbarrier.try_wait.parity.acquire.cta.shared::cta.b64 P1, [%0], %1, 0x989680;\n\t"
                     "@P1 bra.uni WDN_%=;\n\t"
                     "bra.uni WLP_%=;\n\t"
                     "WDN_%=:\n\t}"
                     :: "r"(mbar), "r"(parity) : "memory");
    }
}
DINLINE void tma_load_2d(uint32_t dst, const CUtensorMap* map, int x, int y, uint32_t bar) {
    asm volatile("cp.async.bulk.tensor.2d.shared::cta.global.tile.mbarrier::complete_tx::bytes "
                 "[%0], [%1, {%2, %3}], [%4];"
                 :: "r"(dst), "l"(map), "r"(x), "r"(y), "r"(bar) : "memory");
}
DINLINE void fence_proxy_async() {
    asm volatile("fence.proxy.async.shared::cta;" ::: "memory");
}

DINLINE void ldsm_x4(uint32_t* r, uint32_t addr) {
    asm volatile("ldmatrix.sync.aligned.m8n8.x4.shared.b16 {%0,%1,%2,%3}, [%4];"
                 : "=r"(r[0]), "=r"(r[1]), "=r"(r[2]), "=r"(r[3]) : "r"(addr));
}

DINLINE void mma_16816(float* d, const uint32_t* a, const uint32_t* b) {
    asm volatile("mma.sync.aligned.m16n8k16.row.col.f32.f16.f16.f32 "
                 "{%0,%1,%2,%3}, {%4,%5,%6,%7}, {%8,%9}, {%0,%1,%2,%3};"
                 : "+f"(d[0]), "+f"(d[1]), "+f"(d[2]), "+f"(d[3])
                 : "r"(a[0]), "r"(a[1]), "r"(a[2]), "r"(a[3]), "r"(b[0]), "r"(b[1]));
}

// SW128 swizzle for 128B rows: chunk c (16B) of row r lives at chunk c ^ (r&7)
DINLINE uint32_t swz_off(uint32_t row, uint32_t chunk) {
    return row * 128u + ((chunk ^ (row & 7u)) << 4);
}

// ---------------- dtype detection (inline, per-thread, no global state) ----
// scales are uniform in [0.01, 1.0). Disambiguate fp32 / fp16 / bf16 by range.
DINLINE int detect_flag(const uint32_t* sc_raw) {
    uint32_t ws[4];
    #pragma unroll
    for (int i = 0; i < 4; i++) ws[i] = __ldg(sc_raw + i);
    bool f32ok = true;
    #pragma unroll
    for (int i = 0; i < 4; i++) {
        float f = __uint_as_float(ws[i]);
        f32ok = f32ok && isfinite(f) && f >= 0.004f && f <= 1.1f;
    }
    bool f16ok = true;
    #pragma unroll
    for (int i = 0; i < 4; i++) {
        float a = __half2float(__ushort_as_half((unsigned short)(ws[i] & 0xFFFF)));
        float b = __half2float(__ushort_as_half((unsigned short)(ws[i] >> 16)));
        f16ok = f16ok && a >= 0.004f && a <= 1.02f && b >= 0.004f && b <= 1.02f;
    }
    return f32ok ? 0 : (f16ok ? 1 : 2);
}

DINLINE float load_scalar(const void* p, int idx, int flag) {
    if (flag == 0) return ((const float*)p)[idx];
    if (flag == 1) return __half2float(((const __half*)p)[idx]);
    return __bfloat162float(((const __nv_bfloat16*)p)[idx]);
}

// ---------------- fused prepass kernel ----------------
// blocks [0, NB_CVT)                : x fp32 -> fp16 (2 x float4 -> STG.128)
// blocks [NB_CVT, NB_CVT+NB_DQ)     : dequant (4 packed int32 -> STG.128)
// blocks [NB_CVT+NB_DQ, NB_PRE)     : bias -> fp32
__global__ void __launch_bounds__(256) prepass_kernel(const float4* __restrict__ x,
                                                      const int4* __restrict__ wp4,
                                                      const void* __restrict__ sc,
                                                      const void* __restrict__ bias) {
    const int b = blockIdx.x;
    if (b < NB_CVT) {
        int i = b * 256 + threadIdx.x;
        float4 v0 = __ldcs(x + 2 * i);
        float4 v1 = __ldcs(x + 2 * i + 1);
        __half2 a = __floats2half2_rn(v0.x, v0.y);
        __half2 bb = __floats2half2_rn(v0.z, v0.w);
        __half2 c = __floats2half2_rn(v1.x, v1.y);
        __half2 d = __floats2half2_rn(v1.z, v1.w);
        uint4 o = make_uint4(*reinterpret_cast<unsigned*>(&a),
                             *reinterpret_cast<unsigned*>(&bb),
                             *reinterpret_cast<unsigned*>(&c),
                             *reinterpret_cast<unsigned*>(&d));
        __stcs(reinterpret_cast<uint4*>(g_X) + i, o);
    } else if (b < NB_CVT + NB_DQ) {
        int t = (b - NB_CVT) * 256 + threadIdx.x;    // packed [4t, 4t+4)
        int flag = detect_flag((const uint32_t*)sc);
        int g = t >> 2;
        float s = load_scalar(sc, g, flag);
        int4 v = __ldcs(wp4 + t);
        const int vv[4] = {v.x, v.y, v.z, v.w};
        uint4 o;
        unsigned* ou = reinterpret_cast<unsigned*>(&o);
        #pragma unroll
        for (int i = 0; i < 4; i++) {
            float w0 = ((float)(vv[i] & 7)        * (2.0f / 7.0f) - 1.0f) * s;
            float w1 = ((float)((vv[i] >> 3) & 7) * (2.0f / 7.0f) - 1.0f) * s;
            __half2 h2 = __floats2half2_rn(w0, w1);
            ou[i] = *reinterpret_cast<unsigned*>(&h2);
        }
        size_t elem = ((size_t)(g >> 7) * K_TOTAL) + (size_t)((g & 127) << 5) + ((t & 3) << 3);
        __stcs(reinterpret_cast<uint4*>(g_W) + (elem >> 3), o);
    } else {
        int i = (b - NB_CVT - NB_DQ) * 256 + threadIdx.x;
        int flag = detect_flag((const uint32_t*)sc);
        g_bias[i] = load_scalar(bias, i, flag);
    }
}

// ---------------- GEMM kernel: TMA producer + HMMA consumers ----------------
// 4 warps (2x2), warp tile 64x64, occupancy 2.
__global__ void __launch_bounds__(NTHREADS, 2) gemm_kernel(
    const __grid_constant__ CUtensorMap tma_a,
    const __grid_constant__ CUtensorMap tma_b,
    float* __restrict__ out)           // [M, N]
{
    extern __shared__ __align__(1024) char smem[];
    const uint32_t sb = smem_u32(smem);

    const int tid = threadIdx.x;
    const int wid = tid >> 5, lid = tid & 31;
    const int warp_m = wid & 1;        // 2 warps along M (64 rows each)
    const int warp_n = wid >> 1;       // 2 warps along N (64 cols each)

    // L2-friendly grid swizzle: GROUP_M rows of tiles per super-group (256 CTAs)
    const int bid    = blockIdx.x;
    const int within = bid & (GROUP_M * NT - 1);           // 0..255
    const int mtile  = (bid >> 8) * GROUP_M + (within & (GROUP_M - 1));
    const int ntile  = within >> 3;                        // 0..31

    auto fullb  = [&](int s) { return sb + SMEM_BAR + s * 16; };
    auto emptyb = [&](int s) { return sb + SMEM_BAR + s * 16 + 8; };

    if (tid == 0) {
        #pragma unroll
        for (int s = 0; s < STAGES; s++) {
            mbar_init(fullb(s), 1);    // producer's expect_tx arrive
            mbar_init(emptyb(s), 4);   // one arrive per warp
        }
        fence_proxy_async();
    }
    __syncthreads();

    // prologue: stages 0,1 for kt=0,1
    if (tid == 0) {
        #pragma unroll
        for (int kt = 0; kt < 2; kt++) {
            uint32_t base = sb + SMEM_DATA + kt * STAGE_BYTES;
            mbar_expect_tx(fullb(kt), STAGE_BYTES);
            tma_load_2d(base,           &tma_a, kt * BK, mtile * BM, fullb(kt));
            tma_load_2d(base + A_BYTES, &tma_b, kt * BK, ntile * BN, fullb(kt));
        }
    }

    float acc[4][8][4];
    #pragma unroll
    for (int mt = 0; mt < 4; mt++)
        #pragma unroll
        for (int nt = 0; nt < 8; nt++)
            #pragma unroll
            for (int i = 0; i < 4; i++) acc[mt][nt][i] = 0.0f;

    const int a_row = warp_m * 64 + (lid & 15);                     // + mt*16
    const int a_chk = lid >> 4;                                     // + ks*2
    const int b_row = warp_n * 64 + (lid & 7) + ((lid >> 4) << 3);  // + np*16
    const int b_chk = (lid >> 3) & 1;                               // + ks*2

    #pragma unroll 1
    for (int kt = 0; kt < KTILES; kt++) {
        const int s = kt % 3, u = kt / 3;

        // producer: issue stage for kt+2
        if (tid == 0 && kt + 2 < KTILES) {
            const int kl = kt + 2, sl = kl % 3, ul = kl / 3;
            if (ul > 0) mbar_wait(emptyb(sl), (ul - 1) & 1);
            uint32_t base = sb + SMEM_DATA + sl * STAGE_BYTES;
            mbar_expect_tx(fullb(sl), STAGE_BYTES);
            tma_load_2d(base,           &tma_a, kl * BK, mtile * BM, fullb(sl));
            tma_load_2d(base + A_BYTES, &tma_b, kl * BK, ntile * BN, fullb(sl));
        }

        mbar_wait(fullb(s), u & 1);

        const uint32_t abase = sb + SMEM_DATA + s * STAGE_BYTES;
        const uint32_t bbase = abase + A_BYTES;

        #pragma unroll
        for (int ks = 0; ks < 4; ks++) {
            uint32_t af[4][4];
            #pragma unroll
            for (int mt = 0; mt < 4; mt++)
                ldsm_x4(af[mt], abase + swz_off(a_row + mt * 16, a_chk + ks * 2));

            uint32_t bf[8][2];
            #pragma unroll
            for (int np = 0; np < 4; np++) {
                uint32_t r[4];
                ldsm_x4(r, bbase + swz_off(b_row + np * 16, b_chk + ks * 2));
                bf[2 * np][0] = r[0]; bf[2 * np][1] = r[1];
                bf[2 * np + 1][0] = r[2]; bf[2 * np + 1][1] = r[3];
            }

            #pragma unroll
            for (int mt = 0; mt < 4; mt++)
                #pragma unroll
                for (int nt = 0; nt < 8; nt++)
                    mma_16816(acc[mt][nt], af[mt], bf[nt]);
        }

        if (lid == 0) mbar_arrive(emptyb(s));   // release AFTER all reads consumed
    }

    // ---- epilogue: acc + bias -> out (fp32), streaming stores -------------
    const int orow0 = mtile * BM + warp_m * 64 + (lid >> 2);
    const int ocol0 = ntile * BN + warp_n * 64 + (lid & 3) * 2;

    #pragma unroll
    for (int nt = 0; nt < 8; nt++) {
        float2 bv = *reinterpret_cast<const float2*>(&g_bias[ocol0 + nt * 8]);
        #pragma unroll
        for (int mt = 0; mt < 4; mt++) {
            int r0 = orow0 + mt * 16;
            float* p0 = out + (size_t)r0 * N_TOTAL + ocol0 + nt * 8;
            float* p1 = out + (size_t)(r0 + 8) * N_TOTAL + ocol0 + nt * 8;
            __stcs(reinterpret_cast<float2*>(p0),
                   make_float2(acc[mt][nt][0] + bv.x, acc[mt][nt][1] + bv.y));
            __stcs(reinterpret_cast<float2*>(p1),
                   make_float2(acc[mt][nt][2] + bv.x, acc[mt][nt][3] + bv.y));
        }
    }
}

// ---------------- host launcher ----------------
typedef CUresult (CUDAAPI *EncodeTiledFn)(
    CUtensorMap*, CUtensorMapDataType, cuuint32_t, void*,
    const cuuint64_t*, const cuuint64_t*, const cuuint32_t*, const cuuint32_t*,
    CUtensorMapInterleave, CUtensorMapSwizzle, CUtensorMapL2promotion, CUtensorMapFloatOOBfill);

extern "C" void kernel_launch(void* const* d_in, const int* in_sizes, int n_in,
                              void* d_out, int out_size) {
    const float* x      = (const float*)d_in[0];
    const int*   wp     = (const int*)d_in[1];
    const void*  scales = d_in[2];
    const void*  bias   = d_in[3];
    float*       out    = (float*)d_out;

    void* wptr = nullptr; cudaGetSymbolAddress(&wptr, g_W);
    void* xptr = nullptr; cudaGetSymbolAddress(&xptr, g_X);

    prepass_kernel<<<NB_PRE, 256>>>((const float4*)x, (const int4*)wp, scales, bias);

    // TMA tensormaps (host-side driver entry point; no -lcuda needed)
    EncodeTiledFn encode = nullptr;
    cudaDriverEntryPointQueryResult qres;
    cudaGetDriverEntryPointByVersion("cuTensorMapEncodeTiled", (void**)&encode, 12000,
                                     cudaEnableDefault, &qres);

    CUtensorMap ta, tb;
    {
        cuuint64_t dims[2]    = {(cuuint64_t)K_TOTAL, (cuuint64_t)M_TOTAL};
        cuuint64_t strides[1] = {(cuuint64_t)K_TOTAL * 2};
        cuuint32_t box[2]     = {(cuuint32_t)BK, (cuuint32_t)BM};   // 128B x 128 rows
        cuuint32_t estr[2]    = {1, 1};
        encode(&ta, CU_TENSOR_MAP_DATA_TYPE_FLOAT16, 2, xptr, dims, strides, box, estr,
               CU_TENSOR_MAP_INTERLEAVE_NONE, CU_TENSOR_MAP_SWIZZLE_128B,
               CU_TENSOR_MAP_L2_PROMOTION_L2_128B, CU_TENSOR_MAP_FLOAT_OOB_FILL_NONE);
    }
    {
        cuuint64_t dims[2]    = {(cuuint64_t)K_TOTAL, (cuuint64_t)N_TOTAL};
        cuuint64_t strides[1] = {(cuuint64_t)K_TOTAL * 2};
        cuuint32_t box[2]     = {(cuuint32_t)BK, (cuuint32_t)BN};
        cuuint32_t estr[2]    = {1, 1};
        encode(&tb, CU_TENSOR_MAP_DATA_TYPE_FLOAT16, 2, wptr, dims, strides, box, estr,
               CU_TENSOR_MAP_INTERLEAVE_NONE, CU_TENSOR_MAP_SWIZZLE_128B,
               CU_TENSOR_MAP_L2_PROMOTION_L2_128B, CU_TENSOR_MAP_FLOAT_OOB_FILL_NONE);
    }

    cudaFuncSetAttribute(gemm_kernel, cudaFuncAttributeMaxDynamicSharedMemorySize, SMEM_TOTAL);
    gemm_kernel<<<MT * NT, NTHREADS, SMEM_TOTAL>>>(ta, tb, out);
}

// round 17
// speedup vs baseline: 1.0265x; 1.0188x over previous
#include <cuda.h>
#include <cuda_runtime.h>
#include <cuda_fp16.h>
#include <cuda_bf16.h>
#include <cstdint>

#define DINLINE __device__ __forceinline__

// ---------------- problem constants ----------------
static constexpr int M_TOTAL = 16384;   // 8 * 2048
static constexpr int N_TOTAL = 4096;    // out features
static constexpr int K_TOTAL = 4096;    // in features
static constexpr int NUM_GROUPS = 524288;

// ---------------- GEMM tiling: 4 warps, warp tile 64x64, TMA, occ 2 --------
static constexpr int BM = 128;
static constexpr int BN = 128;
static constexpr int BK = 64;                    // halves per k-tile (128B rows)
static constexpr int KTILES = K_TOTAL / BK;      // 64
static constexpr int STAGES = 3;
static constexpr int MT = M_TOTAL / BM;          // 128
static constexpr int NT = N_TOTAL / BN;          // 32
static constexpr int TILES_TOTAL = MT * NT;      // 4096
static constexpr int GROUP_M = 8;                // supergroup 256 tiles
static constexpr int NTHREADS = 128;             // 4 warps (2x2)

// smem layout: barriers then 1024-aligned tile data (TMA SW128, 128B rows)
static constexpr int A_BYTES      = BM * BK * 2;                 // 16384
static constexpr int STAGE_BYTES  = 2 * A_BYTES;                 // 32768
static constexpr int SMEM_BAR     = 0;     // full[s]=s*16, empty[s]=s*16+8
static constexpr int SMEM_DATA    = 1024;
static constexpr int SMEM_TOTAL   = SMEM_DATA + STAGES * STAGE_BYTES; // 99328 (x2 CTAs ok)

// prepass block partition (one fused kernel, dq interleaved 1-in-5)
static constexpr int NB_CVT  = (M_TOTAL * K_TOTAL / 8) / 256;    // 32768
static constexpr int NB_DQ   = (NUM_GROUPS * 4) / 256;           // 8192
static constexpr int NB_MIX  = NB_CVT + NB_DQ;                   // 40960 (5 * 8192)
static constexpr int NB_BIAS = N_TOTAL / 256;                    // 16
static constexpr int NB_PRE  = NB_MIX + NB_BIAS;

// scratch (device globals: allocation-free scratch per harness rules)
__device__ __align__(1024) __half g_W[(size_t)N_TOTAL * K_TOTAL];  // 32 MB
__device__ __align__(1024) __half g_X[(size_t)M_TOTAL * K_TOTAL];  // 128 MB
__device__ __align__(128) float  g_bias[N_TOTAL];

// ---------------- PTX helpers (compute_103-safe: sm_90 baseline only) ------
DINLINE uint32_t smem_u32(const void* p) {
    uint32_t a;
    asm("{ .reg .u64 t; cvta.to.shared.u64 t, %1; cvt.u32.u64 %0, t; }" : "=r"(a) : "l"(p));
    return a;
}

DINLINE void mbar_init(uint32_t a, uint32_t cnt) {
    asm volatile("mbarrier.init.shared.b64 [%0], %1;" :: "r"(a), "r"(cnt) : "memory");
}
DINLINE void mbar_expect_tx(uint32_t a, uint32_t bytes) {
    asm volatile("mbarrier.arrive.expect_tx.shared.b64 _, [%0], %1;" :: "r"(a), "r"(bytes) : "memory");
}
DINLINE void mbar_arrive(uint32_t a) {
    asm volatile("mbarrier.arrive.shared.b64 _, [%0];" :: "r"(a) : "memory");
}
DINLINE void mbar_wait(uint32_t mbar, uint32_t parity) {
    uint32_t done;
    asm volatile("{\n\t.reg .pred p;\n\t"
                 "mbarrier.try_wait.parity.acquire.cta.shared::cta.b64 p, [%1], %2;\n\t"
                 "selp.b32 %0, 1, 0, p;\n\t}"
                 : "=r"(done) : "r"(mbar), "r"(parity) : "memory");
    if (!done) {
        asm volatile("{\n\t.reg .pred P1;\n\t"
                     "WLP_%=:\n\t"
                     "mbarrier.try_wait.parity.acquire.cta.shared::cta.b64 P1, [%0], %1, 0x989680;\n\t"
                     "@P1 bra.uni WDN_%=;\n\t"
                     "bra.uni WLP_%=;\n\t"
                     "WDN_%=:\n\t}"
                     :: "r"(mbar), "r"(parity) : "memory");
    }
}
DINLINE void tma_load_2d(uint32_t dst, const CUtensorMap* map, int x, int y, uint32_t bar) {
    asm volatile("cp.async.bulk.tensor.2d.shared::cta.global.tile.mbarrier::complete_tx::bytes "
                 "[%0], [%1, {%2, %3}], [%4];"
                 :: "r"(dst), "l"(map), "r"(x), "r"(y), "r"(bar) : "memory");
}
DINLINE void fence_proxy_async() {
    asm volatile("fence.proxy.async.shared::cta;" ::: "memory");
}

DINLINE void ldsm_x4(uint32_t* r, uint32_t addr) {
    asm volatile("ldmatrix.sync.aligned.m8n8.x4.shared.b16 {%0,%1,%2,%3}, [%4];"
                 : "=r"(r[0]), "=r"(r[1]), "=r"(r[2]), "=r"(r[3]) : "r"(addr));
}

DINLINE void mma_16816(float* d, const uint32_t* a, const uint32_t* b) {
    asm volatile("mma.sync.aligned.m16n8k16.row.col.f32.f16.f16.f32 "
                 "{%0,%1,%2,%3}, {%4,%5,%6,%7}, {%8,%9}, {%0,%1,%2,%3};"
                 : "+f"(d[0]), "+f"(d[1]), "+f"(d[2]), "+f"(d[3])
                 : "r"(a[0]), "r"(a[1]), "r"(a[2]), "r"(a[3]), "r"(b[0]), "r"(b[1]));
}

// SW128 swizzle for 128B rows: chunk c (16B) of row r lives at chunk c ^ (r&7)
DINLINE uint32_t swz_off(uint32_t row, uint32_t chunk) {
    return row * 128u + ((chunk ^ (row & 7u)) << 4);
}

// tile index -> (mtile, ntile) with GROUP_M L2 swizzle
DINLINE void tile_coords(int t, int& mtile, int& ntile) {
    int within = t & (GROUP_M * NT - 1);               // 0..255
    mtile = (t >> 8) * GROUP_M + (within & (GROUP_M - 1));
    ntile = within >> 3;
}

// ---------------- dtype detection (inline, per-thread) ----------------
// scales are uniform in [0.01, 1.0). Disambiguate fp32 / fp16 / bf16 by range.
DINLINE int detect_flag(const uint32_t* sc_raw) {
    uint32_t ws[4];
    #pragma unroll
    for (int i = 0; i < 4; i++) ws[i] = __ldg(sc_raw + i);
    bool f32ok = true;
    #pragma unroll
    for (int i = 0; i < 4; i++) {
        float f = __uint_as_float(ws[i]);
        f32ok = f32ok && isfinite(f) && f >= 0.004f && f <= 1.1f;
    }
    bool f16ok = true;
    #pragma unroll
    for (int i = 0; i < 4; i++) {
        float a = __half2float(__ushort_as_half((unsigned short)(ws[i] & 0xFFFF)));
        float b = __half2float(__ushort_as_half((unsigned short)(ws[i] >> 16)));
        f16ok = f16ok && a >= 0.004f && a <= 1.02f && b >= 0.004f && b <= 1.02f;
    }
    return f32ok ? 0 : (f16ok ? 1 : 2);
}

DINLINE float load_scalar(const void* p, int idx, int flag) {
    if (flag == 0) return ((const float*)p)[idx];
    if (flag == 1) return __half2float(((const __half*)p)[idx]);
    return __bfloat162float(((const __nv_bfloat16*)p)[idx]);
}

// ---------------- fused prepass kernel (dq interleaved 1-in-5) -------------
__global__ void __launch_bounds__(256) prepass_kernel(const float4* __restrict__ x,
                                                      const int4* __restrict__ wp4,
                                                      const void* __restrict__ sc,
                                                      const void* __restrict__ bias) {
    const int b = blockIdx.x;
    if (b < NB_MIX) {
        if ((b % 5) == 4) {
            // dequant block: 4 packed int32 per thread -> STG.128
            int t = (b / 5) * 256 + threadIdx.x;
            int flag = detect_flag((const uint32_t*)sc);
            int g = t >> 2;
            float s = load_scalar(sc, g, flag);
            int4 v = __ldcs(wp4 + t);
            const int vv[4] = {v.x, v.y, v.z, v.w};
            uint4 o;
            unsigned* ou = reinterpret_cast<unsigned*>(&o);
            #pragma unroll
            for (int i = 0; i < 4; i++) {
                float w0 = ((float)(vv[i] & 7)        * (2.0f / 7.0f) - 1.0f) * s;
                float w1 = ((float)((vv[i] >> 3) & 7) * (2.0f / 7.0f) - 1.0f) * s;
                __half2 h2 = __floats2half2_rn(w0, w1);
                ou[i] = *reinterpret_cast<unsigned*>(&h2);
            }
            size_t elem = ((size_t)(g >> 7) * K_TOTAL) + (size_t)((g & 127) << 5) + ((t & 3) << 3);
            __stcs(reinterpret_cast<uint4*>(g_W) + (elem >> 3), o);
        } else {
            // cvt block: 2 x float4 -> STG.128
            int i = (b - (b + 1) / 5) * 256 + threadIdx.x;
            float4 v0 = __ldcs(x + 2 * i);
            float4 v1 = __ldcs(x + 2 * i + 1);
            __half2 a = __floats2half2_rn(v0.x, v0.y);
            __half2 bb = __floats2half2_rn(v0.z, v0.w);
            __half2 c = __floats2half2_rn(v1.x, v1.y);
            __half2 d = __floats2half2_rn(v1.z, v1.w);
            uint4 o = make_uint4(*reinterpret_cast<unsigned*>(&a),
                                 *reinterpret_cast<unsigned*>(&bb),
                                 *reinterpret_cast<unsigned*>(&c),
                                 *reinterpret_cast<unsigned*>(&d));
            __stcs(reinterpret_cast<uint4*>(g_X) + i, o);
        }
    } else {
        int i = (b - NB_MIX) * 256 + threadIdx.x;
        int flag = detect_flag((const uint32_t*)sc);
        g_bias[i] = load_scalar(bias, i, flag);
    }
}

// ---------------- GEMM kernel: persistent CTAs, TMA producer + HMMA --------
// Stage ring + barrier parity run on a continuous global step g across tiles:
// the producer's 2-ahead lookahead crosses tile boundaries, so the next
// tile's first stages prefetch during the epilogue.
__global__ void __launch_bounds__(NTHREADS, 2) gemm_kernel(
    const __grid_constant__ CUtensorMap tma_a,
    const __grid_constant__ CUtensorMap tma_b,
    float* __restrict__ out)           // [M, N]
{
    extern __shared__ __align__(1024) char smem[];
    const uint32_t sb = smem_u32(smem);

    const int tid = threadIdx.x;
    const int wid = tid >> 5, lid = tid & 31;
    const int warp_m = wid & 1;        // 2 warps along M (64 rows each)
    const int warp_n = wid >> 1;       // 2 warps along N (64 cols each)

    const int bid   = blockIdx.x;
    const int npers = gridDim.x;
    const int my_tiles = (TILES_TOTAL - bid + npers - 1) / npers;
    const int GTOT = my_tiles * KTILES;

    auto fullb  = [&](int s) { return sb + SMEM_BAR + s * 16; };
    auto emptyb = [&](int s) { return sb + SMEM_BAR + s * 16 + 8; };

    if (tid == 0) {
        #pragma unroll
        for (int s = 0; s < STAGES; s++) {
            mbar_init(fullb(s), 1);    // producer's expect_tx arrive
            mbar_init(emptyb(s), 4);   // one arrive per warp
        }
        fence_proxy_async();
    }
    __syncthreads();

    // prologue: global steps 0,1 (both in first tile; KTILES >= 2)
    if (tid == 0) {
        int m0, n0;
        tile_coords(bid, m0, n0);
        #pragma unroll
        for (int gp = 0; gp < 2; gp++) {
            uint32_t base = sb + SMEM_DATA + gp * STAGE_BYTES;
            mbar_expect_tx(fullb(gp), STAGE_BYTES);
            tma_load_2d(base,           &tma_a, gp * BK, m0 * BM, fullb(gp));
            tma_load_2d(base + A_BYTES, &tma_b, gp * BK, n0 * BN, fullb(gp));
        }
    }

    const int a_row = warp_m * 64 + (lid & 15);                     // + mt*16
    const int a_chk = lid >> 4;                                     // + ks*2
    const int b_row = warp_n * 64 + (lid & 7) + ((lid >> 4) << 3);  // + np*16
    const int b_chk = (lid >> 3) & 1;                               // + ks*2

    int g = 0;
    #pragma unroll 1
    for (int j = 0; j < my_tiles; j++) {
        int mtile, ntile;
        tile_coords(bid + j * npers, mtile, ntile);

        float acc[4][8][4];
        #pragma unroll
        for (int mt = 0; mt < 4; mt++)
            #pragma unroll
            for (int nt = 0; nt < 8; nt++)
                #pragma unroll
                for (int i = 0; i < 4; i++) acc[mt][nt][i] = 0.0f;

        #pragma unroll 1
        for (int kt = 0; kt < KTILES; kt++, g++) {
            // producer: issue global step g+2 (may belong to the next tile)
            const int gl = g + 2;
            if (tid == 0 && gl < GTOT) {
                const int sl = gl % 3, ul = gl / 3;
                if (gl >= STAGES) mbar_wait(emptyb(sl), (ul - 1) & 1);
                int jl = gl >> 6;                 // KTILES = 64
                int ml, nl;
                tile_coords(bid + jl * npers, ml, nl);
                int ktl = gl & (KTILES - 1);
                uint32_t base = sb + SMEM_DATA + sl * STAGE_BYTES;
                mbar_expect_tx(fullb(sl), STAGE_BYTES);
                tma_load_2d(base,           &tma_a, ktl * BK, ml * BM, fullb(sl));
                tma_load_2d(base + A_BYTES, &tma_b, ktl * BK, nl * BN, fullb(sl));
            }

            const int s = g % 3, u = g / 3;
            mbar_wait(fullb(s), u & 1);

            const uint32_t abase = sb + SMEM_DATA + s * STAGE_BYTES;
            const uint32_t bbase = abase + A_BYTES;

            #pragma unroll
            for (int ks = 0; ks < 4; ks++) {
                uint32_t af[4][4];
                #pragma unroll
                for (int mt = 0; mt < 4; mt++)
                    ldsm_x4(af[mt], abase + swz_off(a_row + mt * 16, a_chk + ks * 2));

                uint32_t bf[8][2];
                #pragma unroll
                for (int np = 0; np < 4; np++) {
                    uint32_t r[4];
                    ldsm_x4(r, bbase + swz_off(b_row + np * 16, b_chk + ks * 2));
                    bf[2 * np][0] = r[0]; bf[2 * np][1] = r[1];
                    bf[2 * np + 1][0] = r[2]; bf[2 * np + 1][1] = r[3];
                }

                #pragma unroll
                for (int mt = 0; mt < 4; mt++)
                    #pragma unroll
                    for (int nt = 0; nt < 8; nt++)
                        mma_16816(acc[mt][nt], af[mt], bf[nt]);
            }

            if (lid == 0) mbar_arrive(emptyb(s));   // release AFTER all reads
        }

        // ---- epilogue for this tile (next tile's TMA already in flight) ---
        const int orow0 = mtile * BM + warp_m * 64 + (lid >> 2);
        const int ocol0 = ntile * BN + warp_n * 64 + (lid & 3) * 2;

        #pragma unroll
        for (int nt = 0; nt < 8; nt++) {
            float2 bv = *reinterpret_cast<const float2*>(&g_bias[ocol0 + nt * 8]);
            #pragma unroll
            for (int mt = 0; mt < 4; mt++) {
                int r0 = orow0 + mt * 16;
                float* p0 = out + (size_t)r0 * N_TOTAL + ocol0 + nt * 8;
                float* p1 = out + (size_t)(r0 + 8) * N_TOTAL + ocol0 + nt * 8;
                __stcs(reinterpret_cast<float2*>(p0),
                       make_float2(acc[mt][nt][0] + bv.x, acc[mt][nt][1] + bv.y));
                __stcs(reinterpret_cast<float2*>(p1),
                       make_float2(acc[mt][nt][2] + bv.x, acc[mt][nt][3] + bv.y));
            }
        }
    }
}

// ---------------- host launcher ----------------
typedef CUresult (CUDAAPI *EncodeTiledFn)(
    CUtensorMap*, CUtensorMapDataType, cuuint32_t, void*,
    const cuuint64_t*, const cuuint64_t*, const cuuint32_t*, const cuuint32_t*,
    CUtensorMapInterleave, CUtensorMapSwizzle, CUtensorMapL2promotion, CUtensorMapFloatOOBfill);

extern "C" void kernel_launch(void* const* d_in, const int* in_sizes, int n_in,
                              void* d_out, int out_size) {
    const float* x      = (const float*)d_in[0];
    const int*   wp     = (const int*)d_in[1];
    const void*  scales = d_in[2];
    const void*  bias   = d_in[3];
    float*       out    = (float*)d_out;

    void* wptr = nullptr; cudaGetSymbolAddress(&wptr, g_W);
    void* xptr = nullptr; cudaGetSymbolAddress(&xptr, g_X);

    prepass_kernel<<<NB_PRE, 256>>>((const float4*)x, (const int4*)wp, scales, bias);

    // TMA tensormaps (host-side driver entry point; no -lcuda needed)
    EncodeTiledFn encode = nullptr;
    cudaDriverEntryPointQueryResult qres;
    cudaGetDriverEntryPointByVersion("cuTensorMapEncodeTiled", (void**)&encode, 12000,
                                     cudaEnableDefault, &qres);

    CUtensorMap ta, tb;
    {
        cuuint64_t dims[2]    = {(cuuint64_t)K_TOTAL, (cuuint64_t)M_TOTAL};
        cuuint64_t strides[1] = {(cuuint64_t)K_TOTAL * 2};
        cuuint32_t box[2]     = {(cuuint32_t)BK, (cuuint32_t)BM};   // 128B x 128 rows
        cuuint32_t estr[2]    = {1, 1};
        encode(&ta, CU_TENSOR_MAP_DATA_TYPE_FLOAT16, 2, xptr, dims, strides, box, estr,
               CU_TENSOR_MAP_INTERLEAVE_NONE, CU_TENSOR_MAP_SWIZZLE_128B,
               CU_TENSOR_MAP_L2_PROMOTION_L2_128B, CU_TENSOR_MAP_FLOAT_OOB_FILL_NONE);
    }
    {
        cuuint64_t dims[2]    = {(cuuint64_t)K_TOTAL, (cuuint64_t)N_TOTAL};
        cuuint64_t strides[1] = {(cuuint64_t)K_TOTAL * 2};
        cuuint32_t box[2]     = {(cuuint32_t)BK, (cuuint32_t)BN};
        cuuint32_t estr[2]    = {1, 1};
        encode(&tb, CU_TENSOR_MAP_DATA_TYPE_FLOAT16, 2, wptr, dims, strides, box, estr,
               CU_TENSOR_MAP_INTERLEAVE_NONE, CU_TENSOR_MAP_SWIZZLE_128B,
               CU_TENSOR_MAP_L2_PROMOTION_L2_128B, CU_TENSOR_MAP_FLOAT_OOB_FILL_NONE);
    }

    int nsm = 148;
    cudaDeviceGetAttribute(&nsm, cudaDevAttrMultiProcessorCount, 0);

    cudaFuncSetAttribute(gemm_kernel, cudaFuncAttributeMaxDynamicSharedMemorySize, SMEM_TOTAL);
    gemm_kernel<<<2 * nsm, NTHREADS, SMEM_TOTAL>>>(ta, tb, out);
}